// round 2
// baseline (speedup 1.0000x reference)
#include <cuda_runtime.h>

#define NN 100000
#define EE 1600000
#define HH 128
#define GG 512
#define CC 10
#define LH 384   // L*H
#define EPSV 1e-5f

// ---------------- device scratch (no allocations allowed) ----------------
__device__ __align__(16) float g_hW[NN * HH];     // GEMM output
__device__ __align__(16) float g_aggA[NN * HH];   // aggregation ping
__device__ __align__(16) float g_aggB[NN * HH];   // aggregation pong
__device__ float g_dinv[NN];
__device__ int   g_cnt[NN];
__device__ int   g_off[NN + 1];
__device__ int   g_cursor[NN];
__device__ int   g_srcA[EE];
__device__ float g_wA[EE];
__device__ float g_stat[2 * HH];   // [0:128) sum, [128:256) sumsq
__device__ float g_mean[HH];
__device__ float g_istd[HH];
__device__ int   g_goff[GG + 1];
__device__ float g_pool[GG * LH];
__device__ float g_z[GG * HH];
__device__ float g_m2[HH];
__device__ float g_i2[HH];

// ---------------- setup kernels ----------------
__global__ void k_count(const int* __restrict__ dst) {
    int e = blockIdx.x * blockDim.x + threadIdx.x;
    if (e < EE) atomicAdd(&g_cnt[dst[e]], 1);
}

__global__ void k_dinv() {
    int i = blockIdx.x * blockDim.x + threadIdx.x;
    if (i < NN) g_dinv[i] = rsqrtf((float)(g_cnt[i] + 1));  // +1 self loop
}

__global__ void k_scan() {  // single block, 1024 threads: exclusive scan of g_cnt -> g_off
    __shared__ int wsum[32];
    __shared__ int s_carry;
    int tid = threadIdx.x;
    int lane = tid & 31, wid = tid >> 5;
    if (tid == 0) s_carry = 0;
    __syncthreads();
    for (int base = 0; base < NN; base += 1024) {
        int i = base + tid;
        int v = (i < NN) ? g_cnt[i] : 0;
        int x = v;
        #pragma unroll
        for (int o = 1; o < 32; o <<= 1) {
            int y = __shfl_up_sync(0xffffffffu, x, o);
            if (lane >= o) x += y;
        }
        if (lane == 31) wsum[wid] = x;
        __syncthreads();
        if (wid == 0) {
            int w = wsum[lane];
            int xx = w;
            #pragma unroll
            for (int o = 1; o < 32; o <<= 1) {
                int y = __shfl_up_sync(0xffffffffu, xx, o);
                if (lane >= o) xx += y;
            }
            wsum[lane] = xx - w;  // exclusive warp offsets
        }
        __syncthreads();
        int incl = x + wsum[wid];
        int carry = s_carry;
        if (i < NN) g_off[i] = carry + incl - v;
        __syncthreads();
        if (tid == 1023) s_carry = carry + incl;
        __syncthreads();
    }
    if (tid == 0) g_off[NN] = s_carry;
}

__global__ void k_fill(const int* __restrict__ src, const int* __restrict__ dst) {
    int e = blockIdx.x * blockDim.x + threadIdx.x;
    if (e < EE) {
        int s = src[e], d = dst[e];
        int p = atomicAdd(&g_cursor[d], 1);
        g_srcA[p] = s;
        g_wA[p] = g_dinv[s] * g_dinv[d];
    }
}

__global__ void k_goff(const int* __restrict__ batch) {
    int g = blockIdx.x * blockDim.x + threadIdx.x;
    if (g <= GG) {
        int lo = 0, hi = NN;
        while (lo < hi) {
            int mid = (lo + hi) >> 1;
            if (batch[mid] < g) lo = mid + 1; else hi = mid;
        }
        g_goff[g] = lo;
    }
}

// ---------------- GEMM with optionally fused BN+ReLU on A ----------------
// C[N,128] = act(A)[N,128] @ W[128,128], act = identity or BN+relu using g_mean/g_istd
__global__ __launch_bounds__(256) void k_gemm(const float* __restrict__ A,
                                              const float* __restrict__ W,
                                              float* __restrict__ C,
                                              int doBN,
                                              const float* __restrict__ gamma,
                                              const float* __restrict__ beta) {
    __shared__ float As[8][HH];  // transposed [k][m]
    __shared__ float Bs[8][HH];
    __shared__ float sM[HH], sI[HH], sG[HH], sB[HH];
    int tid = threadIdx.x;
    if (doBN && tid < HH) {
        sM[tid] = g_mean[tid]; sI[tid] = g_istd[tid];
        sG[tid] = gamma[tid];  sB[tid] = beta[tid];
    }
    __syncthreads();
    int tx = tid & 15, ty = tid >> 4;
    int rowBase = blockIdx.x * 128;
    int la_r = tid >> 1;            // 0..127
    int la_k = (tid & 1) * 4;       // 0 or 4
    int lb_k = tid >> 5;            // 0..7
    int lb_n = (tid & 31) * 4;
    float acc[8][8];
    #pragma unroll
    for (int i = 0; i < 8; i++)
        #pragma unroll
        for (int j = 0; j < 8; j++) acc[i][j] = 0.f;
    int arow = rowBase + la_r;
    for (int k0 = 0; k0 < HH; k0 += 8) {
        float4 av = make_float4(0.f, 0.f, 0.f, 0.f);
        if (arow < NN) av = *(const float4*)(A + (size_t)arow * HH + k0 + la_k);
        if (doBN) {
            int kk = k0 + la_k;
            av.x = fmaxf(0.f, (av.x - sM[kk    ]) * sI[kk    ] * sG[kk    ] + sB[kk    ]);
            av.y = fmaxf(0.f, (av.y - sM[kk + 1]) * sI[kk + 1] * sG[kk + 1] + sB[kk + 1]);
            av.z = fmaxf(0.f, (av.z - sM[kk + 2]) * sI[kk + 2] * sG[kk + 2] + sB[kk + 2]);
            av.w = fmaxf(0.f, (av.w - sM[kk + 3]) * sI[kk + 3] * sG[kk + 3] + sB[kk + 3]);
        }
        float4 bv = *(const float4*)(W + (size_t)(k0 + lb_k) * HH + lb_n);
        __syncthreads();
        As[la_k + 0][la_r] = av.x;
        As[la_k + 1][la_r] = av.y;
        As[la_k + 2][la_r] = av.z;
        As[la_k + 3][la_r] = av.w;
        *(float4*)&Bs[lb_k][lb_n] = bv;
        __syncthreads();
        #pragma unroll
        for (int k = 0; k < 8; k++) {
            float ar[8], br[8];
            #pragma unroll
            for (int i = 0; i < 8; i++) ar[i] = As[k][ty * 8 + i];
            #pragma unroll
            for (int j = 0; j < 8; j++) br[j] = Bs[k][tx * 8 + j];
            #pragma unroll
            for (int i = 0; i < 8; i++)
                #pragma unroll
                for (int j = 0; j < 8; j++) acc[i][j] = fmaf(ar[i], br[j], acc[i][j]);
        }
    }
    #pragma unroll
    for (int i = 0; i < 8; i++) {
        int r = rowBase + ty * 8 + i;
        if (r < NN) {
            float4 o0 = make_float4(acc[i][0], acc[i][1], acc[i][2], acc[i][3]);
            float4 o1 = make_float4(acc[i][4], acc[i][5], acc[i][6], acc[i][7]);
            *(float4*)(C + (size_t)r * HH + tx * 8)     = o0;
            *(float4*)(C + (size_t)r * HH + tx * 8 + 4) = o1;
        }
    }
}

// ---------------- aggregation (CSR by dst) + fused BN stat accumulation ----------------
__global__ __launch_bounds__(256) void k_agg(const float* __restrict__ hw,
                                             float* __restrict__ out) {
    __shared__ float s_sum[HH], s_sq[HH];
    int tid = threadIdx.x;
    if (tid < HH) { s_sum[tid] = 0.f; s_sq[tid] = 0.f; }
    __syncthreads();
    int lane = tid & 31;
    int gw = (blockIdx.x * blockDim.x + tid) >> 5;
    int nw = (gridDim.x * blockDim.x) >> 5;
    float lsx = 0.f, lsy = 0.f, lsz = 0.f, lsw = 0.f;
    float lqx = 0.f, lqy = 0.f, lqz = 0.f, lqw = 0.f;
    for (int node = gw; node < NN; node += nw) {
        float dv = g_dinv[node];
        float ws = dv * dv;
        float4 v = ((const float4*)(hw + (size_t)node * HH))[lane];
        float ax = ws * v.x, ay = ws * v.y, az = ws * v.z, aw = ws * v.w;
        int e0 = g_off[node], e1 = g_off[node + 1];
        int e = e0;
        for (; e + 1 < e1; e += 2) {
            int s0 = g_srcA[e],   s1 = g_srcA[e + 1];
            float w0 = g_wA[e],   w1 = g_wA[e + 1];
            float4 u0 = ((const float4*)(hw + (size_t)s0 * HH))[lane];
            float4 u1 = ((const float4*)(hw + (size_t)s1 * HH))[lane];
            ax = fmaf(w0, u0.x, ax); ay = fmaf(w0, u0.y, ay);
            az = fmaf(w0, u0.z, az); aw = fmaf(w0, u0.w, aw);
            ax = fmaf(w1, u1.x, ax); ay = fmaf(w1, u1.y, ay);
            az = fmaf(w1, u1.z, az); aw = fmaf(w1, u1.w, aw);
        }
        if (e < e1) {
            int s0 = g_srcA[e]; float w0 = g_wA[e];
            float4 u0 = ((const float4*)(hw + (size_t)s0 * HH))[lane];
            ax = fmaf(w0, u0.x, ax); ay = fmaf(w0, u0.y, ay);
            az = fmaf(w0, u0.z, az); aw = fmaf(w0, u0.w, aw);
        }
        float4 o = make_float4(ax, ay, az, aw);
        ((float4*)(out + (size_t)node * HH))[lane] = o;
        lsx += ax; lsy += ay; lsz += az; lsw += aw;
        lqx += ax * ax; lqy += ay * ay; lqz += az * az; lqw += aw * aw;
    }
    int c = lane * 4;
    atomicAdd(&s_sum[c], lsx);     atomicAdd(&s_sum[c + 1], lsy);
    atomicAdd(&s_sum[c + 2], lsz); atomicAdd(&s_sum[c + 3], lsw);
    atomicAdd(&s_sq[c], lqx);      atomicAdd(&s_sq[c + 1], lqy);
    atomicAdd(&s_sq[c + 2], lqz);  atomicAdd(&s_sq[c + 3], lqw);
    __syncthreads();
    if (tid < HH) {
        atomicAdd(&g_stat[tid], s_sum[tid]);
        atomicAdd(&g_stat[HH + tid], s_sq[tid]);
    }
}

__global__ void k_fin() {
    int t = threadIdx.x;
    if (t < HH) {
        float m = g_stat[t] * (1.f / NN);
        float v = g_stat[HH + t] * (1.f / NN) - m * m;
        g_mean[t] = m;
        g_istd[t] = rsqrtf(v + EPSV);
    }
}

// per-graph mean pool with fused BN+ReLU
__global__ void k_pool(const float* __restrict__ agg,
                       const float* __restrict__ gamma,
                       const float* __restrict__ beta, int layer) {
    int g = blockIdx.x, c = threadIdx.x;
    int b = g_goff[g], e = g_goff[g + 1];
    float m = g_mean[c], is = g_istd[c], ga = gamma[c], be = beta[c];
    float s = 0.f;
    for (int r = b; r < e; r++) {
        float x = agg[(size_t)r * HH + c];
        s += fmaxf(0.f, (x - m) * is * ga + be);
    }
    int n = e - b;
    float cnt = (float)(n > 1 ? n : 1);
    g_pool[g * LH + layer * HH + c] = s / cnt;
}

// ---------------- MLP head ----------------
__global__ void k_lin1(const float* __restrict__ Wl1, const float* __restrict__ bl1) {
    __shared__ float sp[LH];
    int g = blockIdx.x, t = threadIdx.x;
    sp[t]       = g_pool[g * LH + t];
    sp[t + 128] = g_pool[g * LH + t + 128];
    sp[t + 256] = g_pool[g * LH + t + 256];
    __syncthreads();
    float a = bl1[t];
    #pragma unroll 4
    for (int k = 0; k < LH; k++) a = fmaf(sp[k], Wl1[k * HH + t], a);
    g_z[g * HH + t] = a;
}

__global__ void k_bn2() {
    int t = threadIdx.x;
    if (t < HH) {
        float s = 0.f, q = 0.f;
        for (int r = 0; r < GG; r++) {
            float x = g_z[r * HH + t];
            s += x; q += x * x;
        }
        float m = s * (1.f / GG);
        float v = q * (1.f / GG) - m * m;
        g_m2[t] = m;
        g_i2[t] = rsqrtf(v + EPSV);
    }
}

__global__ void k_final(const float* __restrict__ gl, const float* __restrict__ btl,
                        const float* __restrict__ Wl2, const float* __restrict__ bl2,
                        float* __restrict__ out) {
    __shared__ float zr[HH];
    __shared__ float lg[CC];
    __shared__ float s_ls;
    int g = blockIdx.x, t = threadIdx.x;
    float x = g_z[g * HH + t];
    zr[t] = fmaxf(0.f, (x - g_m2[t]) * g_i2[t] * gl[t] + btl[t]);
    __syncthreads();
    if (t < CC) {
        float d = bl2[t];
        #pragma unroll 4
        for (int j = 0; j < HH; j++) d = fmaf(zr[j], Wl2[j * CC + t], d);
        lg[t] = d;
    }
    __syncthreads();
    if (t == 0) {
        float m = lg[0];
        for (int c = 1; c < CC; c++) m = fmaxf(m, lg[c]);
        float se = 0.f;
        for (int c = 0; c < CC; c++) se += expf(lg[c] - m);
        s_ls = m + logf(se);
    }
    __syncthreads();
    if (t < CC) out[g * CC + t] = lg[t] - s_ls;
}

// ---------------- launch ----------------
extern "C" void kernel_launch(void* const* d_in, const int* in_sizes, int n_in,
                              void* d_out, int out_size) {
    const float* x     = (const float*)d_in[0];
    const int*   ei    = (const int*)d_in[1];     // int32! (JAX x64 disabled)
    const int*   batch = (const int*)d_in[2];
    const float* W1  = (const float*)d_in[3];
    const float* g1  = (const float*)d_in[5];
    const float* bt1 = (const float*)d_in[6];
    const float* Wc  = (const float*)d_in[7];
    const float* gc  = (const float*)d_in[9];
    const float* btc = (const float*)d_in[10];
    const float* Wl1 = (const float*)d_in[11];
    const float* bl1 = (const float*)d_in[12];
    const float* gl  = (const float*)d_in[13];
    const float* btl = (const float*)d_in[14];
    const float* Wl2 = (const float*)d_in[15];
    const float* bl2 = (const float*)d_in[16];
    const int* src = ei;
    const int* dst = ei + EE;

    void *p_cnt, *p_off, *p_cursor, *p_stat, *p_hW, *p_aggA, *p_aggB;
    cudaGetSymbolAddress(&p_cnt, g_cnt);
    cudaGetSymbolAddress(&p_off, g_off);
    cudaGetSymbolAddress(&p_cursor, g_cursor);
    cudaGetSymbolAddress(&p_stat, g_stat);
    cudaGetSymbolAddress(&p_hW, g_hW);
    cudaGetSymbolAddress(&p_aggA, g_aggA);
    cudaGetSymbolAddress(&p_aggB, g_aggB);
    float* hW   = (float*)p_hW;
    float* aggA = (float*)p_aggA;
    float* aggB = (float*)p_aggB;

    // ---- graph setup: degrees, dinv, CSR by dst, graph offsets ----
    cudaMemsetAsync(p_cnt, 0, NN * sizeof(int));
    k_count<<<(EE + 255) / 256, 256>>>(dst);
    k_dinv<<<(NN + 255) / 256, 256>>>();
    k_scan<<<1, 1024>>>();
    cudaMemcpyAsync(p_cursor, p_off, NN * sizeof(int), cudaMemcpyDeviceToDevice);
    k_fill<<<(EE + 255) / 256, 256>>>(src, dst);
    k_goff<<<(GG + 1 + 127) / 128, 128>>>(batch);

    const int GEMM_GRID = (NN + 127) / 128;

    // ---- layer 0: x -> aggA (stats of layer0 in g_mean/g_istd after k_fin) ----
    cudaMemsetAsync(p_stat, 0, 2 * HH * sizeof(float));
    k_gemm<<<GEMM_GRID, 256>>>(x, W1, hW, 0, (const float*)0, (const float*)0);
    k_agg<<<1480, 256>>>(hW, aggA);
    k_fin<<<1, 128>>>();
    k_pool<<<GG, 128>>>(aggA, g1, bt1, 0);

    // ---- layer 1: BN0(aggA) -> aggB ----
    cudaMemsetAsync(p_stat, 0, 2 * HH * sizeof(float));
    k_gemm<<<GEMM_GRID, 256>>>(aggA, Wc, hW, 1, g1, bt1);
    k_agg<<<1480, 256>>>(hW, aggB);
    k_fin<<<1, 128>>>();
    k_pool<<<GG, 128>>>(aggB, gc, btc, 1);

    // ---- layer 2: BN1(aggB) -> aggA ----
    cudaMemsetAsync(p_stat, 0, 2 * HH * sizeof(float));
    k_gemm<<<GEMM_GRID, 256>>>(aggB, Wc + HH * HH, hW, 1, gc, btc);
    k_agg<<<1480, 256>>>(hW, aggA);
    k_fin<<<1, 128>>>();
    k_pool<<<GG, 128>>>(aggA, gc + HH, btc + HH, 2);

    // ---- head ----
    k_lin1<<<GG, 128>>>(Wl1, bl1);
    k_bn2<<<1, 128>>>();
    k_final<<<GG, 128>>>(gl, btl, Wl2, bl2, (float*)d_out);
}

// round 3
// speedup vs baseline: 1.2073x; 1.2073x over previous
#include <cuda_runtime.h>
#include <cstdint>

#define NN 100000
#define EE 1600000
#define HH 128
#define GG 512
#define CC 10
#define LH 384   // L*H
#define EPSV 1e-5f
#define NBLK 98  // ceil(NN/1024)

// ---------------- device scratch (no allocations allowed) ----------------
__device__ __align__(16) float g_hW[NN * HH];     // GEMM output (dinv-scaled)
__device__ __align__(16) float g_aggA[NN * HH];   // aggregation ping
__device__ __align__(16) float g_aggB[NN * HH];   // aggregation pong
__device__ float g_dinv[NN];
__device__ int   g_cnt[NN];
__device__ int   g_off[NN + 1];
__device__ int   g_cursor[NN];
__device__ int   g_srcA[EE];
__device__ int   g_bsum[128];
__device__ int   g_bpre[128];
__device__ float g_stat[2 * HH];   // [0:128) sum, [128:256) sumsq
__device__ float g_mean[HH];
__device__ float g_istd[HH];
__device__ int   g_goff[GG + 1];
__device__ float g_pool[GG * LH];
__device__ float g_z[GG * HH];
__device__ float g_m2[HH];
__device__ float g_i2[HH];

// ---------------- setup kernels ----------------
__global__ void k_count(const int* __restrict__ dst) {
    int e = blockIdx.x * blockDim.x + threadIdx.x;
    if (e < EE) atomicAdd(&g_cnt[dst[e]], 1);
}

// block-local exclusive scan + block sums
__global__ void s_partial() {
    __shared__ int wsum[32];
    int tid = threadIdx.x, lane = tid & 31, wid = tid >> 5;
    int idx = blockIdx.x * 1024 + tid;
    int v = (idx < NN) ? g_cnt[idx] : 0;
    int x = v;
    #pragma unroll
    for (int o = 1; o < 32; o <<= 1) {
        int y = __shfl_up_sync(0xffffffffu, x, o);
        if (lane >= o) x += y;
    }
    if (lane == 31) wsum[wid] = x;
    __syncthreads();
    if (wid == 0) {
        int w = wsum[lane];
        int xx = w;
        #pragma unroll
        for (int o = 1; o < 32; o <<= 1) {
            int y = __shfl_up_sync(0xffffffffu, xx, o);
            if (lane >= o) xx += y;
        }
        wsum[lane] = xx - w;
    }
    __syncthreads();
    int incl = x + wsum[wid];
    if (idx < NN) g_off[idx] = incl - v;     // block-local exclusive
    if (tid == 1023) g_bsum[blockIdx.x] = incl;
}

__global__ void s_scan1() {   // 1 block, 128 threads, scans NBLK partials
    __shared__ int wsum[4];
    int tid = threadIdx.x, lane = tid & 31, wid = tid >> 5;
    int v = (tid < NBLK) ? g_bsum[tid] : 0;
    int x = v;
    #pragma unroll
    for (int o = 1; o < 32; o <<= 1) {
        int y = __shfl_up_sync(0xffffffffu, x, o);
        if (lane >= o) x += y;
    }
    if (lane == 31) wsum[wid] = x;
    __syncthreads();
    int base = 0;
    for (int w = 0; w < wid; w++) base += wsum[w];
    if (tid < NBLK) g_bpre[tid] = base + x - v;  // exclusive
}

__global__ void s_add() {   // finalize offsets, cursor, dinv
    int idx = blockIdx.x * 1024 + threadIdx.x;
    if (idx < NN) {
        int off = g_off[idx] + g_bpre[blockIdx.x];
        g_off[idx] = off;
        g_cursor[idx] = off;
        g_dinv[idx] = rsqrtf((float)(g_cnt[idx] + 1));
    }
    if (idx == 0) g_off[NN] = EE;
}

__global__ void k_fill(const int* __restrict__ src, const int* __restrict__ dst) {
    int e = blockIdx.x * blockDim.x + threadIdx.x;
    if (e < EE) {
        int d = dst[e];
        int p = atomicAdd(&g_cursor[d], 1);
        g_srcA[p] = src[e];
    }
}

__global__ void k_goff(const int* __restrict__ batch) {
    int g = blockIdx.x * blockDim.x + threadIdx.x;
    if (g <= GG) {
        int lo = 0, hi = NN;
        while (lo < hi) {
            int mid = (lo + hi) >> 1;
            if (batch[mid] < g) lo = mid + 1; else hi = mid;
        }
        g_goff[g] = lo;
    }
}

// ---------------- tf32 tensor-core GEMM (3xTF32 split) ----------------
__device__ __forceinline__ float tf32rn(float x) {
    uint32_t u;
    asm("cvt.rna.tf32.f32 %0, %1;" : "=r"(u) : "f"(x));
    return __uint_as_float(u);
}

__device__ __forceinline__ void mma_tf32(float& c0, float& c1, float& c2, float& c3,
                                         uint32_t a0, uint32_t a1, uint32_t a2, uint32_t a3,
                                         uint32_t b0, uint32_t b1) {
    asm volatile("mma.sync.aligned.m16n8k8.row.col.f32.tf32.tf32.f32 "
                 "{%0,%1,%2,%3},{%4,%5,%6,%7},{%8,%9},{%0,%1,%2,%3};"
                 : "+f"(c0), "+f"(c1), "+f"(c2), "+f"(c3)
                 : "r"(a0), "r"(a1), "r"(a2), "r"(a3), "r"(b0), "r"(b1));
}

#define AST 136  // smem stride: 136 mod 32 = 8 -> conflict-free fragment LDS

// C[N,128] = relu(BN(A))[N,128] @ W[128,128], scaled by dinv[row] (hs output)
__global__ __launch_bounds__(256) void k_gemm_t(const float* __restrict__ A,
                                                const float* __restrict__ W,
                                                float* __restrict__ C,
                                                int doBN,
                                                const float* __restrict__ gamma,
                                                const float* __restrict__ beta) {
    __shared__ float sAhi[16][AST];
    __shared__ float sAlo[16][AST];
    __shared__ float sBhi[16][AST];
    __shared__ float sBlo[16][AST];
    __shared__ float sScale[HH], sShift[HH];

    int tid = threadIdx.x;
    if (tid < HH) {
        if (doBN) {
            float is = g_istd[tid] * gamma[tid];
            sScale[tid] = is;
            sShift[tid] = beta[tid] - g_mean[tid] * is;
        } else {
            sScale[tid] = 1.f;
            sShift[tid] = 0.f;
        }
    }
    __syncthreads();

    int lane = tid & 31, wid = tid >> 5;
    int gid = lane >> 2, tig = lane & 3;
    int warp_m = wid & 3, warp_n = wid >> 2;     // 4 x 2 warp grid
    int mrow = warp_m * 32;
    int ncol0 = warp_n * 64;
    int rowBase = blockIdx.x * 128;

    float acc[2][8][4];
    #pragma unroll
    for (int mt = 0; mt < 2; mt++)
        #pragma unroll
        for (int nt = 0; nt < 8; nt++)
            #pragma unroll
            for (int r = 0; r < 4; r++) acc[mt][nt][r] = 0.f;

    for (int kc = 0; kc < 8; kc++) {
        int gcol = kc * 16;
        // load A chunk [128 rows x 16 k] + B chunk [16 k x 128 n]
        float4 av[2]; int arow[2], acol[2];
        #pragma unroll
        for (int i = 0; i < 2; i++) {
            int idx = i * 256 + tid;
            arow[i] = idx & 127;
            acol[i] = (idx >> 7) * 4;
            int gr = rowBase + arow[i];
            float4 v = make_float4(0.f, 0.f, 0.f, 0.f);
            if (gr < NN) v = *(const float4*)(A + (size_t)gr * HH + gcol + acol[i]);
            int cb = gcol + acol[i];
            v.x = fmaxf(0.f, fmaf(v.x, sScale[cb], sShift[cb]));
            v.y = fmaxf(0.f, fmaf(v.y, sScale[cb + 1], sShift[cb + 1]));
            v.z = fmaxf(0.f, fmaf(v.z, sScale[cb + 2], sShift[cb + 2]));
            v.w = fmaxf(0.f, fmaf(v.w, sScale[cb + 3], sShift[cb + 3]));
            if (!doBN) {  // layer0: identity (scale/shift already 1/0, but keep exact path)
                if (gr < NN) v = *(const float4*)(A + (size_t)gr * HH + gcol + acol[i]);
                else v = make_float4(0.f, 0.f, 0.f, 0.f);
            }
            av[i] = v;
        }
        float4 wv[2]; int wk[2], wc[2];
        #pragma unroll
        for (int i = 0; i < 2; i++) {
            int idx = i * 256 + tid;
            wk[i] = idx >> 5;            // 0..15
            wc[i] = (idx & 31) * 4;
            wv[i] = *(const float4*)(W + (size_t)(gcol + wk[i]) * HH + wc[i]);
        }
        __syncthreads();
        #pragma unroll
        for (int i = 0; i < 2; i++) {
            float vv[4] = {av[i].x, av[i].y, av[i].z, av[i].w};
            #pragma unroll
            for (int j = 0; j < 4; j++) {
                float hi = tf32rn(vv[j]);
                sAhi[acol[i] + j][arow[i]] = hi;
                sAlo[acol[i] + j][arow[i]] = tf32rn(vv[j] - hi);
            }
            float wvv[4] = {wv[i].x, wv[i].y, wv[i].z, wv[i].w};
            float4 bh, bl;
            float h0 = tf32rn(wvv[0]), h1 = tf32rn(wvv[1]), h2 = tf32rn(wvv[2]), h3 = tf32rn(wvv[3]);
            bh = make_float4(h0, h1, h2, h3);
            bl = make_float4(tf32rn(wvv[0] - h0), tf32rn(wvv[1] - h1),
                             tf32rn(wvv[2] - h2), tf32rn(wvv[3] - h3));
            *(float4*)&sBhi[wk[i]][wc[i]] = bh;
            *(float4*)&sBlo[wk[i]][wc[i]] = bl;
        }
        __syncthreads();
        #pragma unroll
        for (int ks = 0; ks < 2; ks++) {
            int kb = ks * 8;
            uint32_t ahi[2][4], alo[2][4];
            #pragma unroll
            for (int mt = 0; mt < 2; mt++) {
                int m0 = mrow + mt * 16 + gid;
                ahi[mt][0] = __float_as_uint(sAhi[kb + tig][m0]);
                ahi[mt][1] = __float_as_uint(sAhi[kb + tig][m0 + 8]);
                ahi[mt][2] = __float_as_uint(sAhi[kb + tig + 4][m0]);
                ahi[mt][3] = __float_as_uint(sAhi[kb + tig + 4][m0 + 8]);
                alo[mt][0] = __float_as_uint(sAlo[kb + tig][m0]);
                alo[mt][1] = __float_as_uint(sAlo[kb + tig][m0 + 8]);
                alo[mt][2] = __float_as_uint(sAlo[kb + tig + 4][m0]);
                alo[mt][3] = __float_as_uint(sAlo[kb + tig + 4][m0 + 8]);
            }
            #pragma unroll
            for (int nt = 0; nt < 8; nt++) {
                int nc = ncol0 + nt * 8 + gid;
                uint32_t bh0 = __float_as_uint(sBhi[kb + tig][nc]);
                uint32_t bh1 = __float_as_uint(sBhi[kb + tig + 4][nc]);
                uint32_t bl0 = __float_as_uint(sBlo[kb + tig][nc]);
                uint32_t bl1 = __float_as_uint(sBlo[kb + tig + 4][nc]);
                #pragma unroll
                for (int mt = 0; mt < 2; mt++) {
                    float* c = acc[mt][nt];
                    mma_tf32(c[0], c[1], c[2], c[3], alo[mt][0], alo[mt][1], alo[mt][2], alo[mt][3], bh0, bh1);
                    mma_tf32(c[0], c[1], c[2], c[3], ahi[mt][0], ahi[mt][1], ahi[mt][2], ahi[mt][3], bl0, bl1);
                    mma_tf32(c[0], c[1], c[2], c[3], ahi[mt][0], ahi[mt][1], ahi[mt][2], ahi[mt][3], bh0, bh1);
                }
            }
        }
        __syncthreads();
    }

    // epilogue: scale by dinv[row], write
    #pragma unroll
    for (int mt = 0; mt < 2; mt++) {
        int r0 = rowBase + mrow + mt * 16 + gid;
        int r1 = r0 + 8;
        float dv0 = (r0 < NN) ? g_dinv[r0] : 0.f;
        float dv1 = (r1 < NN) ? g_dinv[r1] : 0.f;
        #pragma unroll
        for (int nt = 0; nt < 8; nt++) {
            int c = ncol0 + nt * 8 + 2 * tig;
            float* a = acc[mt][nt];
            if (r0 < NN) *(float2*)(C + (size_t)r0 * HH + c) = make_float2(a[0] * dv0, a[1] * dv0);
            if (r1 < NN) *(float2*)(C + (size_t)r1 * HH + c) = make_float2(a[2] * dv1, a[3] * dv1);
        }
    }
}

// ---------------- aggregation (CSR by dst) + fused BN stat accumulation ----------------
// out[d] = dinv[d] * ( sum_{s in N(d)} hs[s] + hs[d] ),  hs = g_hW (already dinv-scaled)
__global__ __launch_bounds__(256) void k_agg(const float* __restrict__ hw,
                                             float* __restrict__ out) {
    __shared__ float s_sum[HH], s_sq[HH];
    int tid = threadIdx.x;
    if (tid < HH) { s_sum[tid] = 0.f; s_sq[tid] = 0.f; }
    __syncthreads();
    int lane = tid & 31;
    int gw = (blockIdx.x * blockDim.x + tid) >> 5;
    int nw = (gridDim.x * blockDim.x) >> 5;
    float lsx = 0.f, lsy = 0.f, lsz = 0.f, lsw = 0.f;
    float lqx = 0.f, lqy = 0.f, lqz = 0.f, lqw = 0.f;
    for (int node = gw; node < NN; node += nw) {
        float4 v = ((const float4*)(hw + (size_t)node * HH))[lane];
        float ax = v.x, ay = v.y, az = v.z, aw = v.w;
        int e0 = __ldg(&g_off[node]), e1 = __ldg(&g_off[node + 1]);
        int e = e0;
        for (; e + 4 <= e1; e += 4) {
            int s0 = __ldg(&g_srcA[e]);
            int s1 = __ldg(&g_srcA[e + 1]);
            int s2 = __ldg(&g_srcA[e + 2]);
            int s3 = __ldg(&g_srcA[e + 3]);
            float4 u0 = ((const float4*)(hw + (size_t)s0 * HH))[lane];
            float4 u1 = ((const float4*)(hw + (size_t)s1 * HH))[lane];
            float4 u2 = ((const float4*)(hw + (size_t)s2 * HH))[lane];
            float4 u3 = ((const float4*)(hw + (size_t)s3 * HH))[lane];
            ax += u0.x + u1.x + u2.x + u3.x;
            ay += u0.y + u1.y + u2.y + u3.y;
            az += u0.z + u1.z + u2.z + u3.z;
            aw += u0.w + u1.w + u2.w + u3.w;
        }
        for (; e < e1; e++) {
            int s0 = __ldg(&g_srcA[e]);
            float4 u0 = ((const float4*)(hw + (size_t)s0 * HH))[lane];
            ax += u0.x; ay += u0.y; az += u0.z; aw += u0.w;
        }
        float dv = g_dinv[node];
        ax *= dv; ay *= dv; az *= dv; aw *= dv;
        ((float4*)(out + (size_t)node * HH))[lane] = make_float4(ax, ay, az, aw);
        lsx += ax; lsy += ay; lsz += az; lsw += aw;
        lqx += ax * ax; lqy += ay * ay; lqz += az * az; lqw += aw * aw;
    }
    int c = lane * 4;
    atomicAdd(&s_sum[c], lsx);     atomicAdd(&s_sum[c + 1], lsy);
    atomicAdd(&s_sum[c + 2], lsz); atomicAdd(&s_sum[c + 3], lsw);
    atomicAdd(&s_sq[c], lqx);      atomicAdd(&s_sq[c + 1], lqy);
    atomicAdd(&s_sq[c + 2], lqz);  atomicAdd(&s_sq[c + 3], lqw);
    __syncthreads();
    if (tid < HH) {
        atomicAdd(&g_stat[tid], s_sum[tid]);
        atomicAdd(&g_stat[HH + tid], s_sq[tid]);
    }
}

__global__ void k_fin() {
    int t = threadIdx.x;
    if (t < HH) {
        float m = g_stat[t] * (1.f / NN);
        float v = g_stat[HH + t] * (1.f / NN) - m * m;
        g_mean[t] = m;
        g_istd[t] = rsqrtf(v + EPSV);
    }
}

// per-graph mean pool with fused BN+ReLU
__global__ void k_pool(const float* __restrict__ agg,
                       const float* __restrict__ gamma,
                       const float* __restrict__ beta, int layer) {
    int g = blockIdx.x, c = threadIdx.x;
    int b = g_goff[g], e = g_goff[g + 1];
    float is = g_istd[c] * gamma[c];
    float sh = beta[c] - g_mean[c] * is;
    float s = 0.f;
    for (int r = b; r < e; r++) {
        float x = agg[(size_t)r * HH + c];
        s += fmaxf(0.f, fmaf(x, is, sh));
    }
    int n = e - b;
    float cnt = (float)(n > 1 ? n : 1);
    g_pool[g * LH + layer * HH + c] = s / cnt;
}

// ---------------- MLP head ----------------
__global__ void k_lin1(const float* __restrict__ Wl1, const float* __restrict__ bl1) {
    __shared__ float sp[LH];
    int g = blockIdx.x, t = threadIdx.x;
    sp[t]       = g_pool[g * LH + t];
    sp[t + 128] = g_pool[g * LH + t + 128];
    sp[t + 256] = g_pool[g * LH + t + 256];
    __syncthreads();
    float a = bl1[t];
    #pragma unroll 4
    for (int k = 0; k < LH; k++) a = fmaf(sp[k], Wl1[k * HH + t], a);
    g_z[g * HH + t] = a;
}

__global__ void k_bn2() {
    int t = threadIdx.x;
    if (t < HH) {
        float s = 0.f, q = 0.f;
        for (int r = 0; r < GG; r++) {
            float x = g_z[r * HH + t];
            s += x; q += x * x;
        }
        float m = s * (1.f / GG);
        float v = q * (1.f / GG) - m * m;
        g_m2[t] = m;
        g_i2[t] = rsqrtf(v + EPSV);
    }
}

__global__ void k_final(const float* __restrict__ gl, const float* __restrict__ btl,
                        const float* __restrict__ Wl2, const float* __restrict__ bl2,
                        float* __restrict__ out) {
    __shared__ float zr[HH];
    __shared__ float lg[CC];
    __shared__ float s_ls;
    int g = blockIdx.x, t = threadIdx.x;
    float x = g_z[g * HH + t];
    zr[t] = fmaxf(0.f, (x - g_m2[t]) * g_i2[t] * gl[t] + btl[t]);
    __syncthreads();
    if (t < CC) {
        float d = bl2[t];
        #pragma unroll 4
        for (int j = 0; j < HH; j++) d = fmaf(zr[j], Wl2[j * CC + t], d);
        lg[t] = d;
    }
    __syncthreads();
    if (t == 0) {
        float m = lg[0];
        for (int c = 1; c < CC; c++) m = fmaxf(m, lg[c]);
        float se = 0.f;
        for (int c = 0; c < CC; c++) se += expf(lg[c] - m);
        s_ls = m + logf(se);
    }
    __syncthreads();
    if (t < CC) out[g * CC + t] = lg[t] - s_ls;
}

// ---------------- launch ----------------
extern "C" void kernel_launch(void* const* d_in, const int* in_sizes, int n_in,
                              void* d_out, int out_size) {
    const float* x     = (const float*)d_in[0];
    const int*   ei    = (const int*)d_in[1];     // int32 (JAX x64 disabled)
    const int*   batch = (const int*)d_in[2];
    const float* W1  = (const float*)d_in[3];
    const float* g1  = (const float*)d_in[5];
    const float* bt1 = (const float*)d_in[6];
    const float* Wc  = (const float*)d_in[7];
    const float* gc  = (const float*)d_in[9];
    const float* btc = (const float*)d_in[10];
    const float* Wl1 = (const float*)d_in[11];
    const float* bl1 = (const float*)d_in[12];
    const float* gl  = (const float*)d_in[13];
    const float* btl = (const float*)d_in[14];
    const float* Wl2 = (const float*)d_in[15];
    const float* bl2 = (const float*)d_in[16];
    const int* src = ei;
    const int* dst = ei + EE;

    void *p_cnt, *p_stat, *p_hW, *p_aggA, *p_aggB;
    cudaGetSymbolAddress(&p_cnt, g_cnt);
    cudaGetSymbolAddress(&p_stat, g_stat);
    cudaGetSymbolAddress(&p_hW, g_hW);
    cudaGetSymbolAddress(&p_aggA, g_aggA);
    cudaGetSymbolAddress(&p_aggB, g_aggB);
    float* hW   = (float*)p_hW;
    float* aggA = (float*)p_aggA;
    float* aggB = (float*)p_aggB;

    // ---- graph setup: degrees, dinv, CSR by dst, graph offsets ----
    cudaMemsetAsync(p_cnt, 0, NN * sizeof(int));
    k_count<<<(EE + 255) / 256, 256>>>(dst);
    s_partial<<<NBLK, 1024>>>();
    s_scan1<<<1, 128>>>();
    s_add<<<NBLK, 1024>>>();
    k_fill<<<(EE + 255) / 256, 256>>>(src, dst);
    k_goff<<<(GG + 1 + 127) / 128, 128>>>(batch);

    const int GEMM_GRID = (NN + 127) / 128;

    // ---- layer 0: x -> aggA ----
    cudaMemsetAsync(p_stat, 0, 2 * HH * sizeof(float));
    k_gemm_t<<<GEMM_GRID, 256>>>(x, W1, hW, 0, (const float*)0, (const float*)0);
    k_agg<<<1480, 256>>>(hW, aggA);
    k_fin<<<1, 128>>>();
    k_pool<<<GG, 128>>>(aggA, g1, bt1, 0);

    // ---- layer 1: BN0(aggA) -> aggB ----
    cudaMemsetAsync(p_stat, 0, 2 * HH * sizeof(float));
    k_gemm_t<<<GEMM_GRID, 256>>>(aggA, Wc, hW, 1, g1, bt1);
    k_agg<<<1480, 256>>>(hW, aggB);
    k_fin<<<1, 128>>>();
    k_pool<<<GG, 128>>>(aggB, gc, btc, 1);

    // ---- layer 2: BN1(aggB) -> aggA ----
    cudaMemsetAsync(p_stat, 0, 2 * HH * sizeof(float));
    k_gemm_t<<<GEMM_GRID, 256>>>(aggB, Wc + HH * HH, hW, 1, gc, btc);
    k_agg<<<1480, 256>>>(hW, aggA);
    k_fin<<<1, 128>>>();
    k_pool<<<GG, 128>>>(aggA, gc + HH, btc + HH, 2);

    // ---- head ----
    k_lin1<<<GG, 128>>>(Wl1, bl1);
    k_bn2<<<1, 128>>>();
    k_final<<<GG, 128>>>(gl, btl, Wl2, bl2, (float*)d_out);
}